// round 1
// baseline (speedup 1.0000x reference)
#include <cuda_runtime.h>
#include <cstdint>

#define NMAX    100000
#define IN_DIM  512
#define HID     16

// Scratch (allocation-free per harness rules): __device__ globals.
__device__ float g_xw[(size_t)NMAX * HID];   // x @ W1           [N,16]
__device__ float g_h [(size_t)NMAX * HID];   // spmm accumulator [N,16]
__device__ float g_h2[(size_t)NMAX];         // relu(h+b1) @ W2  [N]

// ---------------------------------------------------------------------------
// K0: zero the spmm-1 accumulator
// ---------------------------------------------------------------------------
__global__ void k_zero_h(int n4) {
    int i = blockIdx.x * blockDim.x + threadIdx.x;
    if (i < n4) ((float4*)g_h)[i] = make_float4(0.f, 0.f, 0.f, 0.f);
}

// ---------------------------------------------------------------------------
// K1: g_xw = x @ W1   (thread per row, W1 in shared, packed f32x2 FMA)
// ---------------------------------------------------------------------------
__global__ void k_gemm1(const float* __restrict__ x,
                        const float* __restrict__ W1, int n) {
    __shared__ float sW[IN_DIM * HID];                 // 32 KB
    for (int i = threadIdx.x; i < IN_DIM * HID / 4; i += blockDim.x)
        ((float4*)sW)[i] = ((const float4*)W1)[i];
    __syncthreads();

    int row = blockIdx.x * blockDim.x + threadIdx.x;
    if (row >= n) return;

    unsigned long long acc[8];                          // 8 x f32x2 = 16 cols
#pragma unroll
    for (int q = 0; q < 8; ++q) acc[q] = 0ull;

    const float4* xr = (const float4*)(x + (size_t)row * IN_DIM);
#pragma unroll 2
    for (int k4 = 0; k4 < IN_DIM / 4; ++k4) {
        float4 v = xr[k4];
        float xs[4] = {v.x, v.y, v.z, v.w};
#pragma unroll
        for (int kk = 0; kk < 4; ++kk) {
            int k = k4 * 4 + kk;
            unsigned long long xx;
            asm("mov.b64 %0, {%1, %1};" : "=l"(xx) : "f"(xs[kk]));
            const ulonglong2* w2 = (const ulonglong2*)(sW + k * HID);
#pragma unroll
            for (int p = 0; p < 4; ++p) {
                ulonglong2 wv = w2[p];
                asm("fma.rn.f32x2 %0, %1, %2, %0;"
                    : "+l"(acc[2 * p])     : "l"(xx), "l"(wv.x));
                asm("fma.rn.f32x2 %0, %1, %2, %0;"
                    : "+l"(acc[2 * p + 1]) : "l"(xx), "l"(wv.y));
            }
        }
    }

    unsigned long long* o =
        (unsigned long long*)(g_xw + (size_t)row * HID);
#pragma unroll
    for (int q = 0; q < 8; ++q) o[q] = acc[q];
}

// ---------------------------------------------------------------------------
// K2: g_h[dst] += w * g_xw[src]   (4 threads/edge, vector RED)
// ---------------------------------------------------------------------------
__global__ void k_spmm1(const int*   __restrict__ src,
                        const int*   __restrict__ dst,
                        const float* __restrict__ w, int E) {
    int t = blockIdx.x * blockDim.x + threadIdx.x;
    int e = t >> 2;
    if (e >= E) return;
    int part = t & 3;

    int   s  = __ldg(src + e);
    int   d  = __ldg(dst + e);
    float we = __ldg(w   + e);

    float4 v = __ldg(((const float4*)g_xw) + (size_t)s * 4 + part);
    float a = v.x * we, b = v.y * we, c = v.z * we, dd = v.w * we;

    float* addr = g_h + (size_t)d * HID + part * 4;
    asm volatile("red.global.add.v4.f32 [%0], {%1, %2, %3, %4};"
                 :: "l"(addr), "f"(a), "f"(b), "f"(c), "f"(dd)
                 : "memory");
}

// ---------------------------------------------------------------------------
// K3: g_h2 = relu(g_h + b1) @ W2 ; out init to b2
// ---------------------------------------------------------------------------
__global__ void k_layer2a(const float* __restrict__ b1,
                          const float* __restrict__ W2,
                          const float* __restrict__ b2,
                          float* __restrict__ out, int n) {
    int i = blockIdx.x * blockDim.x + threadIdx.x;
    if (i >= n) return;
    float acc = 0.f;
#pragma unroll
    for (int p = 0; p < 4; ++p) {
        float4 hv = ((const float4*)g_h)[(size_t)i * 4 + p];
        float4 bv = __ldg(((const float4*)b1) + p);
        float4 wv = __ldg(((const float4*)W2) + p);
        acc += fmaxf(hv.x + bv.x, 0.f) * wv.x
             + fmaxf(hv.y + bv.y, 0.f) * wv.y
             + fmaxf(hv.z + bv.z, 0.f) * wv.z
             + fmaxf(hv.w + bv.w, 0.f) * wv.w;
    }
    g_h2[i] = acc;
    out[i]  = __ldg(b2);      // out starts at bias; K4 atomically accumulates
}

// ---------------------------------------------------------------------------
// K4: out[dst] += w * g_h2[src]   (scalar RED, 1 thread/edge)
// ---------------------------------------------------------------------------
__global__ void k_spmm2(const int*   __restrict__ src,
                        const int*   __restrict__ dst,
                        const float* __restrict__ w,
                        float* __restrict__ out, int E) {
    int e = blockIdx.x * blockDim.x + threadIdx.x;
    if (e >= E) return;
    atomicAdd(out + __ldg(dst + e), __ldg(w + e) * __ldg(g_h2 + __ldg(src + e)));
}

// ---------------------------------------------------------------------------
extern "C" void kernel_launch(void* const* d_in, const int* in_sizes, int n_in,
                              void* d_out, int out_size) {
    const float* x   = (const float*)d_in[0];
    const int*   src = (const int*)  d_in[1];
    const int*   dst = (const int*)  d_in[2];
    const float* w   = (const float*)d_in[3];
    const float* W1  = (const float*)d_in[4];
    const float* b1  = (const float*)d_in[5];
    const float* W2  = (const float*)d_in[6];
    const float* b2  = (const float*)d_in[7];
    float* out = (float*)d_out;

    int N = in_sizes[0] / IN_DIM;
    int E = in_sizes[1];

    const int T = 256;

    // K0: zero h accumulator
    int n4 = N * HID / 4;
    k_zero_h<<<(n4 + T - 1) / T, T>>>(n4);

    // K1: xw = x @ W1
    k_gemm1<<<(N + T - 1) / T, T>>>(x, W1, N);

    // K2: h += scatter(w * xw[src]) by dst
    long long t2 = (long long)E * 4;
    k_spmm1<<<(unsigned)((t2 + T - 1) / T), T>>>(src, dst, w, E);

    // K3: h2 = relu(h + b1) @ W2 ; out = b2
    k_layer2a<<<(N + T - 1) / T, T>>>(b1, W2, b2, out, N);

    // K4: out += scatter(w * h2[src]) by dst
    k_spmm2<<<(E + T - 1) / T, T>>>(src, dst, w, out, E);
}